// round 10
// baseline (speedup 1.0000x reference)
#include <cuda_runtime.h>
#include <math.h>
#include <float.h>

#define BATCH 1024
#define ED 128
#define MAXN 200
#define PAD_IDX 100000
#define LN_EPS 1e-5f
#define FULLM 0xffffffffu

__global__ __launch_bounds__(512, 2) void entity_encoder_kernel(
    const int*   __restrict__ entity,
    const int*   __restrict__ conn_left,
    const int*   __restrict__ conn_right,
    const float* __restrict__ emb,
    const float* __restrict__ W_bil,
    const float* __restrict__ W_tail,
    const float* __restrict__ W_head,
    const float* __restrict__ gamma,
    const float* __restrict__ beta,
    float*       __restrict__ out)
{
    const int b    = blockIdx.x;
    const int tid  = threadIdx.x;
    const int wid  = tid >> 5;
    const int lane = tid & 31;
    const int side = wid >> 3;      // 0 = left, 1 = right
    const int sw   = wid & 7;       // warp within side

    __shared__ float s_wr[ED];
    __shared__ float s_head[2][ED];
    __shared__ float s_qp[512];
    __shared__ float s_q[ED];
    __shared__ int2  s_conn[2][MAXN];
    __shared__ float s_part[16][ED];
    __shared__ float s_zw[16];
    __shared__ float s_agg[2][ED];
    __shared__ float s_x[2][ED];
    __shared__ float s_redA[16];
    __shared__ float s_redB[16];
    __shared__ float s_stat[2][2];

    // ---- stage conn pairs (coalesced, both sides) ----
    {
        const int2* cl = (const int2*)(conn_left  + (long)b * MAXN * 2);
        const int2* cr = (const int2*)(conn_right + (long)b * MAXN * 2);
        for (int i = tid; i < MAXN; i += 512) {
            s_conn[0][i] = cl[i];
            s_conn[1][i] = cr[i];
        }
    }

    // ---- head / weak_rel ----
    const int e0 = entity[b * 2 + 0];
    const int e1 = entity[b * 2 + 1];
    if (tid < ED) {
        float a = emb[(long)e0 * ED + tid];
        float c = emb[(long)e1 * ED + tid];
        s_wr[tid]      = c - a;
        s_head[0][tid] = a;
        s_head[1][tid] = c;
    }
    __syncthreads();

    // ---- q[e] = sum_d wr[d] * W_bil[d, e]  (4-way d-split over 512 thr) ----
    {
        const int e  = tid & (ED - 1);
        const int qq = tid >> 7;
        const int d0 = qq * 32;
        float acc = 0.f;
        #pragma unroll 8
        for (int d = 0; d < 32; ++d)
            acc = fmaf(s_wr[d0 + d], W_bil[(d0 + d) * ED + e], acc);
        s_qp[tid] = acc;
    }
    __syncthreads();
    if (tid < ED)
        s_q[tid] = s_qp[tid] + s_qp[ED + tid] + s_qp[2 * ED + tid] + s_qp[3 * ED + tid];
    __syncthreads();

    // ---- SINGLE merged pass: score + UNSHIFTED exp aggregate ----
    // scores are O(1e-2): exp(v) cannot overflow; softmax is shift-invariant.
    {
        const float4 q4 = ((const float4*)s_q)[lane];
        const int2*  cn = s_conn[side];

        float  wz  = 0.f;
        float4 acc = make_float4(0.f, 0.f, 0.f, 0.f);

        #pragma unroll 1
        for (int g = 0; g < 6; ++g) {
            const int mb = sw + 32 * g;
            int2 c4[4];
            #pragma unroll
            for (int i = 0; i < 4; ++i) c4[i] = cn[mb + 8 * i];
            float4 r[4], t[4];
            #pragma unroll
            for (int i = 0; i < 4; ++i)
                r[i] = ((const float4*)(emb + (long)c4[i].x * ED))[lane];
            #pragma unroll
            for (int i = 0; i < 4; ++i)
                t[i] = ((const float4*)(emb + (long)c4[i].y * ED))[lane];
            #pragma unroll
            for (int i = 0; i < 4; ++i) {
                float v = q4.x * r[i].x + q4.y * r[i].y + q4.z * r[i].z + q4.w * r[i].w;
                v += __shfl_xor_sync(FULLM, v, 16);
                v += __shfl_xor_sync(FULLM, v, 8);
                v += __shfl_xor_sync(FULLM, v, 4);
                v += __shfl_xor_sync(FULLM, v, 2);
                v += __shfl_xor_sync(FULLM, v, 1);
                float e = (c4[i].x == PAD_IDX) ? 0.f : __expf(v);
                wz   += e;
                acc.x = fmaf(e, t[i].x, acc.x);
                acc.y = fmaf(e, t[i].y, acc.y);
                acc.z = fmaf(e, t[i].z, acc.z);
                acc.w = fmaf(e, t[i].w, acc.w);
            }
        }
        {   // tail neighbor m = 192 + sw
            const int2 c1 = cn[192 + sw];
            float4 r = ((const float4*)(emb + (long)c1.x * ED))[lane];
            float4 t = ((const float4*)(emb + (long)c1.y * ED))[lane];
            float v = q4.x * r.x + q4.y * r.y + q4.z * r.z + q4.w * r.w;
            v += __shfl_xor_sync(FULLM, v, 16);
            v += __shfl_xor_sync(FULLM, v, 8);
            v += __shfl_xor_sync(FULLM, v, 4);
            v += __shfl_xor_sync(FULLM, v, 2);
            v += __shfl_xor_sync(FULLM, v, 1);
            float e = (c1.x == PAD_IDX) ? 0.f : __expf(v);
            wz   += e;
            acc.x = fmaf(e, t.x, acc.x);
            acc.y = fmaf(e, t.y, acc.y);
            acc.z = fmaf(e, t.z, acc.z);
            acc.w = fmaf(e, t.w, acc.w);
        }
        ((float4*)s_part[wid])[lane] = acc;
        if (lane == 0) s_zw[wid] = wz;
    }
    __syncthreads();

    // ---- cross-warp combine; normalize once ----
    if (tid < 256) {
        const int sR = tid >> 7;
        const int t  = tid & (ED - 1);
        float sum = 0.f, Z = 0.f;
        #pragma unroll
        for (int w = 0; w < 8; ++w) {
            sum += s_part[sR * 8 + w][t];
            Z   += s_zw[sR * 8 + w];
        }
        s_agg[sR][t] = sum * (1.f / Z);
    }
    __syncthreads();

    // ---- h = relu(agg.W_tail^T + head.W_head^T) for BOTH sides ----
    {
        const float4 aL = ((const float4*)s_agg[0])[lane];
        const float4 hL = ((const float4*)s_head[0])[lane];
        const float4 aR = ((const float4*)s_agg[1])[lane];
        const float4 hR = ((const float4*)s_head[1])[lane];
        #pragma unroll 1
        for (int i0 = wid; i0 < ED; i0 += 32) {
            const int i1 = i0 + 16;
            float4 wt0 = ((const float4*)(W_tail + i0 * ED))[lane];
            float4 wh0 = ((const float4*)(W_head + i0 * ED))[lane];
            float4 wt1 = ((const float4*)(W_tail + i1 * ED))[lane];
            float4 wh1 = ((const float4*)(W_head + i1 * ED))[lane];
            float vL0 = aL.x * wt0.x + aL.y * wt0.y + aL.z * wt0.z + aL.w * wt0.w
                      + hL.x * wh0.x + hL.y * wh0.y + hL.z * wh0.z + hL.w * wh0.w;
            float vR0 = aR.x * wt0.x + aR.y * wt0.y + aR.z * wt0.z + aR.w * wt0.w
                      + hR.x * wh0.x + hR.y * wh0.y + hR.z * wh0.z + hR.w * wh0.w;
            float vL1 = aL.x * wt1.x + aL.y * wt1.y + aL.z * wt1.z + aL.w * wt1.w
                      + hL.x * wh1.x + hL.y * wh1.y + hL.z * wh1.z + hL.w * wh1.w;
            float vR1 = aR.x * wt1.x + aR.y * wt1.y + aR.z * wt1.z + aR.w * wt1.w
                      + hR.x * wh1.x + hR.y * wh1.y + hR.z * wh1.z + hR.w * wh1.w;
            #pragma unroll
            for (int d = 16; d >= 1; d >>= 1) {
                vL0 += __shfl_xor_sync(FULLM, vL0, d);
                vR0 += __shfl_xor_sync(FULLM, vR0, d);
                vL1 += __shfl_xor_sync(FULLM, vL1, d);
                vR1 += __shfl_xor_sync(FULLM, vR1, d);
            }
            if (lane == 0) {
                s_x[0][i0] = fmaxf(vL0, 0.f) + s_head[0][i0];
                s_x[1][i0] = fmaxf(vR0, 0.f) + s_head[1][i0];
                s_x[0][i1] = fmaxf(vL1, 0.f) + s_head[0][i1];
                s_x[1][i1] = fmaxf(vR1, 0.f) + s_head[1][i1];
            }
        }
    }
    __syncthreads();

    // ---- two LayerNorms in parallel ----
    if (tid < 256) {
        const int sL = tid >> 7;
        const int t  = tid & (ED - 1);
        const int w4 = t >> 5;
        float xv = s_x[sL][t];
        float s1 = xv, s2 = xv * xv;
        #pragma unroll
        for (int d = 16; d >= 1; d >>= 1) {
            s1 += __shfl_xor_sync(FULLM, s1, d);
            s2 += __shfl_xor_sync(FULLM, s2, d);
        }
        if (lane == 0) { s_redA[sL * 8 + w4] = s1; s_redB[sL * 8 + w4] = s2; }
    }
    __syncthreads();
    if (tid < 256) {
        const int sL = tid >> 7;
        const int t  = tid & (ED - 1);
        if (t == 0) {
            float t1 = 0.f, t2 = 0.f;
            #pragma unroll
            for (int w = 0; w < 4; ++w) { t1 += s_redA[sL * 8 + w]; t2 += s_redB[sL * 8 + w]; }
            float mu  = t1 * (1.f / ED);
            float var = t2 * (1.f / ED) - mu * mu;
            s_stat[sL][0] = mu;
            s_stat[sL][1] = rsqrtf(var + LN_EPS);
        }
    }
    __syncthreads();
    if (tid < 256) {
        const int sL = tid >> 7;
        const int t  = tid & (ED - 1);
        float mu = s_stat[sL][0], rstd = s_stat[sL][1];
        float o = (s_x[sL][t] - mu) * rstd * gamma[t] + beta[t];
        out[((long)sL * BATCH + b) * ED + t] = o;
    }
}

extern "C" void kernel_launch(void* const* d_in, const int* in_sizes, int n_in,
                              void* d_out, int out_size) {
    (void)in_sizes; (void)n_in; (void)out_size;
    const int*   entity     = (const int*)  d_in[0];
    const int*   conn_left  = (const int*)  d_in[1];
    const int*   conn_right = (const int*)  d_in[2];
    const float* emb        = (const float*)d_in[3];
    const float* W_bil      = (const float*)d_in[4];
    const float* W_tail     = (const float*)d_in[5];
    const float* W_head     = (const float*)d_in[6];
    const float* gamma      = (const float*)d_in[7];
    const float* beta       = (const float*)d_in[8];
    float* out = (float*)d_out;

    entity_encoder_kernel<<<BATCH, 512>>>(entity, conn_left, conn_right, emb,
                                          W_bil, W_tail, W_head, gamma, beta, out);
}

// round 11
// speedup vs baseline: 1.3728x; 1.3728x over previous
#include <cuda_runtime.h>
#include <math.h>
#include <float.h>

#define BATCH 1024
#define ED 128
#define MAXN 200
#define PAD_IDX 100000
#define LN_EPS 1e-5f
#define FULLM 0xffffffffu

// scratch: q = wr @ W_bil, and head embeddings (left/right)
__device__ float g_q[BATCH * ED];
__device__ float g_head[2 * BATCH * ED];

// ---------- prep: heads + q for all b ----------
#define PREP_ROWS 8
__global__ __launch_bounds__(128) void prep_kernel(
    const int*   __restrict__ entity,
    const float* __restrict__ emb,
    const float* __restrict__ W_bil)
{
    const int bb  = blockIdx.x * PREP_ROWS;
    const int tid = threadIdx.x;

    __shared__ float s_wr[PREP_ROWS][ED];
    __shared__ int   s_ids[2 * PREP_ROWS];

    if (tid < 2 * PREP_ROWS) s_ids[tid] = entity[bb * 2 + tid];
    __syncthreads();

    #pragma unroll
    for (int rb = 0; rb < PREP_ROWS; ++rb) {
        float a = emb[(long)s_ids[2 * rb]     * ED + tid];
        float c = emb[(long)s_ids[2 * rb + 1] * ED + tid];
        s_wr[rb][tid] = c - a;
        g_head[((long)0 * BATCH + bb + rb) * ED + tid] = a;
        g_head[((long)1 * BATCH + bb + rb) * ED + tid] = c;
    }
    __syncthreads();

    float acc[PREP_ROWS];
    #pragma unroll
    for (int i = 0; i < PREP_ROWS; ++i) acc[i] = 0.f;

    #pragma unroll 1
    for (int d = 0; d < ED; d += 4) {
        float w0 = W_bil[(d + 0) * ED + tid];
        float w1 = W_bil[(d + 1) * ED + tid];
        float w2 = W_bil[(d + 2) * ED + tid];
        float w3 = W_bil[(d + 3) * ED + tid];
        #pragma unroll
        for (int rb = 0; rb < PREP_ROWS; ++rb) {
            const float4 wr4 = *(const float4*)&s_wr[rb][d];
            acc[rb] = fmaf(wr4.x, w0, acc[rb]);
            acc[rb] = fmaf(wr4.y, w1, acc[rb]);
            acc[rb] = fmaf(wr4.z, w2, acc[rb]);
            acc[rb] = fmaf(wr4.w, w3, acc[rb]);
        }
    }
    #pragma unroll
    for (int rb = 0; rb < PREP_ROWS; ++rb)
        g_q[(bb + rb) * ED + tid] = acc[rb];
}

// ---------- main: gather + online softmax + branch + LN ----------
__global__ __launch_bounds__(512, 2) void entity_encoder_kernel(
    const int*   __restrict__ conn_left,
    const int*   __restrict__ conn_right,
    const float* __restrict__ emb,
    const float* __restrict__ W_tail,
    const float* __restrict__ W_head,
    const float* __restrict__ gamma,
    const float* __restrict__ beta,
    float*       __restrict__ out)
{
    const int b    = blockIdx.x;
    const int tid  = threadIdx.x;
    const int wid  = tid >> 5;
    const int lane = tid & 31;
    const int side = wid >> 3;
    const int sw   = wid & 7;

    __shared__ float s_head[2][ED];
    __shared__ float s_q[ED];
    __shared__ int2  s_conn[2][MAXN];
    __shared__ float s_part[16][ED];
    __shared__ float s_mw[16];
    __shared__ float s_zw[16];
    __shared__ float s_agg[2][ED];
    __shared__ float s_x[2][ED];
    __shared__ float s_redA[16];
    __shared__ float s_redB[16];
    __shared__ float s_stat[2][2];

    // ---- stage conn pairs + q + heads (coalesced) ----
    {
        const int2* cl = (const int2*)(conn_left  + (long)b * MAXN * 2);
        const int2* cr = (const int2*)(conn_right + (long)b * MAXN * 2);
        for (int i = tid; i < MAXN; i += 512) {
            s_conn[0][i] = cl[i];
            s_conn[1][i] = cr[i];
        }
        if (tid < ED) {
            s_q[tid] = g_q[b * ED + tid];
        } else if (tid < 384) {
            const int sL = (tid - ED) >> 7;
            const int t  = tid & (ED - 1);
            s_head[sL][t] = g_head[((long)sL * BATCH + b) * ED + t];
        }
    }
    __syncthreads();

    // ---- SINGLE merged pass: score + online-softmax aggregate (R9 body) ----
    {
        const float4 q4 = ((const float4*)s_q)[lane];
        const int2*  cn = s_conn[side];

        float  wm  = -FLT_MAX;
        float  wz  = 0.f;
        float4 acc = make_float4(0.f, 0.f, 0.f, 0.f);

        #pragma unroll 1
        for (int g = 0; g < 6; ++g) {
            const int mb = sw + 32 * g;
            int2 c4[4];
            #pragma unroll
            for (int i = 0; i < 4; ++i) c4[i] = cn[mb + 8 * i];
            float4 r[4], t[4];
            #pragma unroll
            for (int i = 0; i < 4; ++i)
                r[i] = ((const float4*)(emb + (long)c4[i].x * ED))[lane];
            #pragma unroll
            for (int i = 0; i < 4; ++i)
                t[i] = ((const float4*)(emb + (long)c4[i].y * ED))[lane];
            #pragma unroll
            for (int i = 0; i < 4; ++i) {
                float v = q4.x * r[i].x + q4.y * r[i].y + q4.z * r[i].z + q4.w * r[i].w;
                v += __shfl_xor_sync(FULLM, v, 16);
                v += __shfl_xor_sync(FULLM, v, 8);
                v += __shfl_xor_sync(FULLM, v, 4);
                v += __shfl_xor_sync(FULLM, v, 2);
                v += __shfl_xor_sync(FULLM, v, 1);
                if (c4[i].x == PAD_IDX) v = -FLT_MAX;
                const float mn = fmaxf(wm, v);
                const float cc = __expf(wm - mn);
                const float e  = __expf(v - mn);
                wm = mn;
                wz = wz * cc + e;
                acc.x = fmaf(acc.x, cc, e * t[i].x);
                acc.y = fmaf(acc.y, cc, e * t[i].y);
                acc.z = fmaf(acc.z, cc, e * t[i].z);
                acc.w = fmaf(acc.w, cc, e * t[i].w);
            }
        }
        {   // tail neighbor m = 192 + sw
            const int2 c1 = cn[192 + sw];
            float4 r = ((const float4*)(emb + (long)c1.x * ED))[lane];
            float4 t = ((const float4*)(emb + (long)c1.y * ED))[lane];
            float v = q4.x * r.x + q4.y * r.y + q4.z * r.z + q4.w * r.w;
            v += __shfl_xor_sync(FULLM, v, 16);
            v += __shfl_xor_sync(FULLM, v, 8);
            v += __shfl_xor_sync(FULLM, v, 4);
            v += __shfl_xor_sync(FULLM, v, 2);
            v += __shfl_xor_sync(FULLM, v, 1);
            if (c1.x == PAD_IDX) v = -FLT_MAX;
            const float mn = fmaxf(wm, v);
            const float cc = __expf(wm - mn);
            const float e  = __expf(v - mn);
            wm = mn;
            wz = wz * cc + e;
            acc.x = fmaf(acc.x, cc, e * t.x);
            acc.y = fmaf(acc.y, cc, e * t.y);
            acc.z = fmaf(acc.z, cc, e * t.z);
            acc.w = fmaf(acc.w, cc, e * t.w);
        }
        ((float4*)s_part[wid])[lane] = acc;
        if (lane == 0) { s_mw[wid] = wm; s_zw[wid] = wz; }
    }
    __syncthreads();

    // ---- cross-warp combine with max-correction; normalize once ----
    if (tid < 256) {
        const int sR = tid >> 7;
        const int t  = tid & (ED - 1);
        float M = -FLT_MAX;
        #pragma unroll
        for (int w = 0; w < 8; ++w) M = fmaxf(M, s_mw[sR * 8 + w]);
        float sum = 0.f, Z = 0.f;
        #pragma unroll
        for (int w = 0; w < 8; ++w) {
            const float sc = __expf(s_mw[sR * 8 + w] - M);
            sum = fmaf(sc, s_part[sR * 8 + w][t], sum);
            Z   = fmaf(sc, s_zw[sR * 8 + w], Z);
        }
        s_agg[sR][t] = sum * (1.f / Z);
    }
    __syncthreads();

    // ---- h = relu(agg.W_tail^T + head.W_head^T) for BOTH sides ----
    {
        const float4 aL = ((const float4*)s_agg[0])[lane];
        const float4 hL = ((const float4*)s_head[0])[lane];
        const float4 aR = ((const float4*)s_agg[1])[lane];
        const float4 hR = ((const float4*)s_head[1])[lane];
        #pragma unroll 1
        for (int i0 = wid; i0 < ED; i0 += 32) {
            const int i1 = i0 + 16;
            float4 wt0 = ((const float4*)(W_tail + i0 * ED))[lane];
            float4 wh0 = ((const float4*)(W_head + i0 * ED))[lane];
            float4 wt1 = ((const float4*)(W_tail + i1 * ED))[lane];
            float4 wh1 = ((const float4*)(W_head + i1 * ED))[lane];
            float vL0 = aL.x * wt0.x + aL.y * wt0.y + aL.z * wt0.z + aL.w * wt0.w
                      + hL.x * wh0.x + hL.y * wh0.y + hL.z * wh0.z + hL.w * wh0.w;
            float vR0 = aR.x * wt0.x + aR.y * wt0.y + aR.z * wt0.z + aR.w * wt0.w
                      + hR.x * wh0.x + hR.y * wh0.y + hR.z * wh0.z + hR.w * wh0.w;
            float vL1 = aL.x * wt1.x + aL.y * wt1.y + aL.z * wt1.z + aL.w * wt1.w
                      + hL.x * wh1.x + hL.y * wh1.y + hL.z * wh1.z + hL.w * wh1.w;
            float vR1 = aR.x * wt1.x + aR.y * wt1.y + aR.z * wt1.z + aR.w * wt1.w
                      + hR.x * wh1.x + hR.y * wh1.y + hR.z * wh1.z + hR.w * wh1.w;
            #pragma unroll
            for (int d = 16; d >= 1; d >>= 1) {
                vL0 += __shfl_xor_sync(FULLM, vL0, d);
                vR0 += __shfl_xor_sync(FULLM, vR0, d);
                vL1 += __shfl_xor_sync(FULLM, vL1, d);
                vR1 += __shfl_xor_sync(FULLM, vR1, d);
            }
            if (lane == 0) {
                s_x[0][i0] = fmaxf(vL0, 0.f) + s_head[0][i0];
                s_x[1][i0] = fmaxf(vR0, 0.f) + s_head[1][i0];
                s_x[0][i1] = fmaxf(vL1, 0.f) + s_head[0][i1];
                s_x[1][i1] = fmaxf(vR1, 0.f) + s_head[1][i1];
            }
        }
    }
    __syncthreads();

    // ---- two LayerNorms in parallel ----
    if (tid < 256) {
        const int sL = tid >> 7;
        const int t  = tid & (ED - 1);
        const int w4 = t >> 5;
        float xv = s_x[sL][t];
        float s1 = xv, s2 = xv * xv;
        #pragma unroll
        for (int d = 16; d >= 1; d >>= 1) {
            s1 += __shfl_xor_sync(FULLM, s1, d);
            s2 += __shfl_xor_sync(FULLM, s2, d);
        }
        if (lane == 0) { s_redA[sL * 8 + w4] = s1; s_redB[sL * 8 + w4] = s2; }
    }
    __syncthreads();
    if (tid < 256) {
        const int sL = tid >> 7;
        const int t  = tid & (ED - 1);
        if (t == 0) {
            float t1 = 0.f, t2 = 0.f;
            #pragma unroll
            for (int w = 0; w < 4; ++w) { t1 += s_redA[sL * 8 + w]; t2 += s_redB[sL * 8 + w]; }
            float mu  = t1 * (1.f / ED);
            float var = t2 * (1.f / ED) - mu * mu;
            s_stat[sL][0] = mu;
            s_stat[sL][1] = rsqrtf(var + LN_EPS);
        }
    }
    __syncthreads();
    if (tid < 256) {
        const int sL = tid >> 7;
        const int t  = tid & (ED - 1);
        float mu = s_stat[sL][0], rstd = s_stat[sL][1];
        float o = (s_x[sL][t] - mu) * rstd * gamma[t] + beta[t];
        out[((long)sL * BATCH + b) * ED + t] = o;
    }
}

extern "C" void kernel_launch(void* const* d_in, const int* in_sizes, int n_in,
                              void* d_out, int out_size) {
    (void)in_sizes; (void)n_in; (void)out_size;
    const int*   entity     = (const int*)  d_in[0];
    const int*   conn_left  = (const int*)  d_in[1];
    const int*   conn_right = (const int*)  d_in[2];
    const float* emb        = (const float*)d_in[3];
    const float* W_bil      = (const float*)d_in[4];
    const float* W_tail     = (const float*)d_in[5];
    const float* W_head     = (const float*)d_in[6];
    const float* gamma      = (const float*)d_in[7];
    const float* beta       = (const float*)d_in[8];
    float* out = (float*)d_out;

    prep_kernel<<<BATCH / PREP_ROWS, 128>>>(entity, emb, W_bil);
    entity_encoder_kernel<<<BATCH, 512>>>(conn_left, conn_right, emb,
                                          W_tail, W_head, gamma, beta, out);
}

// round 13
// speedup vs baseline: 1.5255x; 1.1112x over previous
#include <cuda_runtime.h>
#include <math.h>
#include <float.h>

#define BATCH 1024
#define ED 128
#define MAXN 200
#define PAD_IDX 100000
#define LN_EPS 1e-5f
#define FULLM 0xffffffffu

// scratch: q = wr @ W_bil, and head embeddings (left/right)
__device__ float g_q[BATCH * ED];
__device__ float g_head[2 * BATCH * ED];

// ---------- prep: heads + q for all b (latency-optimized) ----------
#define PREP_ROWS 4
__global__ __launch_bounds__(256) void prep_kernel(
    const int*   __restrict__ entity,
    const float* __restrict__ emb,
    const float* __restrict__ W_bil)
{
    const int bb  = blockIdx.x * PREP_ROWS;
    const int tid = threadIdx.x;
    const int e   = tid & (ED - 1);
    const int dh  = tid >> 7;            // 0 or 1 : d-half
    const int d0  = dh * 64;

    __shared__ float s_wr[PREP_ROWS][ED];
    __shared__ float s_part[2][PREP_ROWS][ED];
    __shared__ int   s_ids[2 * PREP_ROWS];

    if (tid < 2 * PREP_ROWS) s_ids[tid] = entity[bb * 2 + tid];
    __syncthreads();

    // stage heads + wr : 256 threads, 2 rows each half
    {
        const int rbase = dh * 2;        // rows {0,1} or {2,3}
        #pragma unroll
        for (int r = 0; r < 2; ++r) {
            const int rb = rbase + r;
            float a = emb[(long)s_ids[2 * rb]     * ED + e];
            float c = emb[(long)s_ids[2 * rb + 1] * ED + e];
            s_wr[rb][e] = c - a;
            g_head[((long)0 * BATCH + bb + rb) * ED + e] = a;
            g_head[((long)1 * BATCH + bb + rb) * ED + e] = c;
        }
    }
    __syncthreads();

    // q partial over this thread's 64 d's, 16 loads in flight per chunk
    float acc0 = 0.f, acc1 = 0.f, acc2 = 0.f, acc3 = 0.f;
    #pragma unroll
    for (int c = 0; c < 4; ++c) {
        const int dc = d0 + c * 16;
        float w[16];
        #pragma unroll
        for (int j = 0; j < 16; ++j)
            w[j] = W_bil[(dc + j) * ED + e];
        #pragma unroll
        for (int j = 0; j < 16; ++j) {
            const int d = dc + j;
            acc0 = fmaf(s_wr[0][d], w[j], acc0);
            acc1 = fmaf(s_wr[1][d], w[j], acc1);
            acc2 = fmaf(s_wr[2][d], w[j], acc2);
            acc3 = fmaf(s_wr[3][d], w[j], acc3);
        }
    }
    s_part[dh][0][e] = acc0;
    s_part[dh][1][e] = acc1;
    s_part[dh][2][e] = acc2;
    s_part[dh][3][e] = acc3;
    __syncthreads();

    // combine halves: each thread-half writes 2 rows
    {
        const int rbase = dh * 2;
        #pragma unroll
        for (int r = 0; r < 2; ++r) {
            const int rb = rbase + r;
            g_q[(long)(bb + rb) * ED + e] = s_part[0][rb][e] + s_part[1][rb][e];
        }
    }
}

// ---------- main: gather + online softmax + branch + LN ----------
__global__ __launch_bounds__(512, 2) void entity_encoder_kernel(
    const int*   __restrict__ conn_left,
    const int*   __restrict__ conn_right,
    const float* __restrict__ emb,
    const float* __restrict__ W_tail,
    const float* __restrict__ W_head,
    const float* __restrict__ gamma,
    const float* __restrict__ beta,
    float*       __restrict__ out)
{
    const int b    = blockIdx.x;
    const int tid  = threadIdx.x;
    const int wid  = tid >> 5;
    const int lane = tid & 31;
    const int side = wid >> 3;
    const int sw   = wid & 7;

    __shared__ float s_head[2][ED];
    __shared__ float s_q[ED];
    __shared__ int2  s_conn[2][MAXN];
    __shared__ float s_part[16][ED];
    __shared__ float s_mw[16];
    __shared__ float s_zw[16];
    __shared__ float s_agg[2][ED];
    __shared__ float s_x[2][ED];
    __shared__ float s_redA[16];
    __shared__ float s_redB[16];
    __shared__ float s_stat[2][2];

    // ---- stage conn pairs + q + heads (coalesced) ----
    {
        const int2* cl = (const int2*)(conn_left  + (long)b * MAXN * 2);
        const int2* cr = (const int2*)(conn_right + (long)b * MAXN * 2);
        for (int i = tid; i < MAXN; i += 512) {
            s_conn[0][i] = cl[i];
            s_conn[1][i] = cr[i];
        }
        if (tid < ED) {
            s_q[tid] = g_q[b * ED + tid];
        } else if (tid < 384) {
            const int sL = (tid - ED) >> 7;
            const int t  = tid & (ED - 1);
            s_head[sL][t] = g_head[((long)sL * BATCH + b) * ED + t];
        }
    }
    __syncthreads();

    // ---- SINGLE merged pass: score + online-softmax aggregate ----
    {
        const float4 q4 = ((const float4*)s_q)[lane];
        const int2*  cn = s_conn[side];

        float  wm  = -FLT_MAX;
        float  wz  = 0.f;
        float4 acc = make_float4(0.f, 0.f, 0.f, 0.f);

        #pragma unroll 1
        for (int g = 0; g < 6; ++g) {
            const int mb = sw + 32 * g;
            int2 c4[4];
            #pragma unroll
            for (int i = 0; i < 4; ++i) c4[i] = cn[mb + 8 * i];
            float4 r[4], t[4];
            #pragma unroll
            for (int i = 0; i < 4; ++i)
                r[i] = ((const float4*)(emb + (long)c4[i].x * ED))[lane];
            #pragma unroll
            for (int i = 0; i < 4; ++i)
                t[i] = ((const float4*)(emb + (long)c4[i].y * ED))[lane];
            #pragma unroll
            for (int i = 0; i < 4; ++i) {
                float v = q4.x * r[i].x + q4.y * r[i].y + q4.z * r[i].z + q4.w * r[i].w;
                v += __shfl_xor_sync(FULLM, v, 16);
                v += __shfl_xor_sync(FULLM, v, 8);
                v += __shfl_xor_sync(FULLM, v, 4);
                v += __shfl_xor_sync(FULLM, v, 2);
                v += __shfl_xor_sync(FULLM, v, 1);
                if (c4[i].x == PAD_IDX) v = -FLT_MAX;
                const float mn = fmaxf(wm, v);
                const float cc = __expf(wm - mn);
                const float e  = __expf(v - mn);
                wm = mn;
                wz = wz * cc + e;
                acc.x = fmaf(acc.x, cc, e * t[i].x);
                acc.y = fmaf(acc.y, cc, e * t[i].y);
                acc.z = fmaf(acc.z, cc, e * t[i].z);
                acc.w = fmaf(acc.w, cc, e * t[i].w);
            }
        }
        {   // tail neighbor m = 192 + sw
            const int2 c1 = cn[192 + sw];
            float4 r = ((const float4*)(emb + (long)c1.x * ED))[lane];
            float4 t = ((const float4*)(emb + (long)c1.y * ED))[lane];
            float v = q4.x * r.x + q4.y * r.y + q4.z * r.z + q4.w * r.w;
            v += __shfl_xor_sync(FULLM, v, 16);
            v += __shfl_xor_sync(FULLM, v, 8);
            v += __shfl_xor_sync(FULLM, v, 4);
            v += __shfl_xor_sync(FULLM, v, 2);
            v += __shfl_xor_sync(FULLM, v, 1);
            if (c1.x == PAD_IDX) v = -FLT_MAX;
            const float mn = fmaxf(wm, v);
            const float cc = __expf(wm - mn);
            const float e  = __expf(v - mn);
            wm = mn;
            wz = wz * cc + e;
            acc.x = fmaf(acc.x, cc, e * t.x);
            acc.y = fmaf(acc.y, cc, e * t.y);
            acc.z = fmaf(acc.z, cc, e * t.z);
            acc.w = fmaf(acc.w, cc, e * t.w);
        }
        ((float4*)s_part[wid])[lane] = acc;
        if (lane == 0) { s_mw[wid] = wm; s_zw[wid] = wz; }
    }
    __syncthreads();

    // ---- cross-warp combine with max-correction; normalize once ----
    if (tid < 256) {
        const int sR = tid >> 7;
        const int t  = tid & (ED - 1);
        float M = -FLT_MAX;
        #pragma unroll
        for (int w = 0; w < 8; ++w) M = fmaxf(M, s_mw[sR * 8 + w]);
        float sum = 0.f, Z = 0.f;
        #pragma unroll
        for (int w = 0; w < 8; ++w) {
            const float sc = __expf(s_mw[sR * 8 + w] - M);
            sum = fmaf(sc, s_part[sR * 8 + w][t], sum);
            Z   = fmaf(sc, s_zw[sR * 8 + w], Z);
        }
        s_agg[sR][t] = sum * (1.f / Z);
    }
    __syncthreads();

    // ---- h = relu(agg.W_tail^T + head.W_head^T) for BOTH sides ----
    {
        const float4 aL = ((const float4*)s_agg[0])[lane];
        const float4 hL = ((const float4*)s_head[0])[lane];
        const float4 aR = ((const float4*)s_agg[1])[lane];
        const float4 hR = ((const float4*)s_head[1])[lane];
        #pragma unroll 1
        for (int i0 = wid; i0 < ED; i0 += 32) {
            const int i1 = i0 + 16;
            float4 wt0 = ((const float4*)(W_tail + i0 * ED))[lane];
            float4 wh0 = ((const float4*)(W_head + i0 * ED))[lane];
            float4 wt1 = ((const float4*)(W_tail + i1 * ED))[lane];
            float4 wh1 = ((const float4*)(W_head + i1 * ED))[lane];
            float vL0 = aL.x * wt0.x + aL.y * wt0.y + aL.z * wt0.z + aL.w * wt0.w
                      + hL.x * wh0.x + hL.y * wh0.y + hL.z * wh0.z + hL.w * wh0.w;
            float vR0 = aR.x * wt0.x + aR.y * wt0.y + aR.z * wt0.z + aR.w * wt0.w
                      + hR.x * wh0.x + hR.y * wh0.y + hR.z * wh0.z + hR.w * wh0.w;
            float vL1 = aL.x * wt1.x + aL.y * wt1.y + aL.z * wt1.z + aL.w * wt1.w
                      + hL.x * wh1.x + hL.y * wh1.y + hL.z * wh1.z + hL.w * wh1.w;
            float vR1 = aR.x * wt1.x + aR.y * wt1.y + aR.z * wt1.z + aR.w * wt1.w
                      + hR.x * wh1.x + hR.y * wh1.y + hR.z * wh1.z + hR.w * wh1.w;
            #pragma unroll
            for (int d = 16; d >= 1; d >>= 1) {
                vL0 += __shfl_xor_sync(FULLM, vL0, d);
                vR0 += __shfl_xor_sync(FULLM, vR0, d);
                vL1 += __shfl_xor_sync(FULLM, vL1, d);
                vR1 += __shfl_xor_sync(FULLM, vR1, d);
            }
            if (lane == 0) {
                s_x[0][i0] = fmaxf(vL0, 0.f) + s_head[0][i0];
                s_x[1][i0] = fmaxf(vR0, 0.f) + s_head[1][i0];
                s_x[0][i1] = fmaxf(vL1, 0.f) + s_head[0][i1];
                s_x[1][i1] = fmaxf(vR1, 0.f) + s_head[1][i1];
            }
        }
    }
    __syncthreads();

    // ---- two LayerNorms in parallel ----
    if (tid < 256) {
        const int sL = tid >> 7;
        const int t  = tid & (ED - 1);
        const int w4 = t >> 5;
        float xv = s_x[sL][t];
        float s1 = xv, s2 = xv * xv;
        #pragma unroll
        for (int d = 16; d >= 1; d >>= 1) {
            s1 += __shfl_xor_sync(FULLM, s1, d);
            s2 += __shfl_xor_sync(FULLM, s2, d);
        }
        if (lane == 0) { s_redA[sL * 8 + w4] = s1; s_redB[sL * 8 + w4] = s2; }
    }
    __syncthreads();
    if (tid < 256) {
        const int sL = tid >> 7;
        const int t  = tid & (ED - 1);
        if (t == 0) {
            float t1 = 0.f, t2 = 0.f;
            #pragma unroll
            for (int w = 0; w < 4; ++w) { t1 += s_redA[sL * 8 + w]; t2 += s_redB[sL * 8 + w]; }
            float mu  = t1 * (1.f / ED);
            float var = t2 * (1.f / ED) - mu * mu;
            s_stat[sL][0] = mu;
            s_stat[sL][1] = rsqrtf(var + LN_EPS);
        }
    }
    __syncthreads();
    if (tid < 256) {
        const int sL = tid >> 7;
        const int t  = tid & (ED - 1);
        float mu = s_stat[sL][0], rstd = s_stat[sL][1];
        float o = (s_x[sL][t] - mu) * rstd * gamma[t] + beta[t];
        out[((long)sL * BATCH + b) * ED + t] = o;
    }
}

extern "C" void kernel_launch(void* const* d_in, const int* in_sizes, int n_in,
                              void* d_out, int out_size) {
    (void)in_sizes; (void)n_in; (void)out_size;
    const int*   entity     = (const int*)  d_in[0];
    const int*   conn_left  = (const int*)  d_in[1];
    const int*   conn_right = (const int*)  d_in[2];
    const float* emb        = (const float*)d_in[3];
    const float* W_bil      = (const float*)d_in[4];
    const float* W_tail     = (const float*)d_in[5];
    const float* W_head     = (const float*)d_in[6];
    const float* gamma      = (const float*)d_in[7];
    const float* beta       = (const float*)d_in[8];
    float* out = (float*)d_out;

    prep_kernel<<<BATCH / PREP_ROWS, 256>>>(entity, emb, W_bil);
    entity_encoder_kernel<<<BATCH, 512>>>(conn_left, conn_right, emb,
                                          W_tail, W_head, gamma, beta, out);
}

// round 14
// speedup vs baseline: 1.5744x; 1.0321x over previous
#include <cuda_runtime.h>
#include <math.h>
#include <float.h>

#define BATCH 1024
#define ED 128
#define MAXN 200
#define PAD_IDX 100000
#define LN_EPS 1e-5f
#define FULLM 0xffffffffu

// scratch: q = wr @ W_bil, and head embeddings (left/right)
__device__ float g_q[BATCH * ED];
__device__ float g_head[2 * BATCH * ED];

// ---------- prep: heads + q for all b (latency-optimized) ----------
#define PREP_ROWS 4
__global__ __launch_bounds__(256) void prep_kernel(
    const int*   __restrict__ entity,
    const float* __restrict__ emb,
    const float* __restrict__ W_bil)
{
    const int bb  = blockIdx.x * PREP_ROWS;
    const int tid = threadIdx.x;
    const int e   = tid & (ED - 1);
    const int dh  = tid >> 7;            // 0 or 1 : d-half
    const int d0  = dh * 64;

    __shared__ float s_wr[PREP_ROWS][ED];
    __shared__ float s_part[2][PREP_ROWS][ED];
    __shared__ int   s_ids[2 * PREP_ROWS];

    if (tid < 2 * PREP_ROWS) s_ids[tid] = entity[bb * 2 + tid];
    __syncthreads();

    {
        const int rbase = dh * 2;
        #pragma unroll
        for (int r = 0; r < 2; ++r) {
            const int rb = rbase + r;
            float a = emb[(long)s_ids[2 * rb]     * ED + e];
            float c = emb[(long)s_ids[2 * rb + 1] * ED + e];
            s_wr[rb][e] = c - a;
            g_head[((long)0 * BATCH + bb + rb) * ED + e] = a;
            g_head[((long)1 * BATCH + bb + rb) * ED + e] = c;
        }
    }
    __syncthreads();

    float acc0 = 0.f, acc1 = 0.f, acc2 = 0.f, acc3 = 0.f;
    #pragma unroll
    for (int c = 0; c < 4; ++c) {
        const int dc = d0 + c * 16;
        float w[16];
        #pragma unroll
        for (int j = 0; j < 16; ++j)
            w[j] = W_bil[(dc + j) * ED + e];
        #pragma unroll
        for (int j = 0; j < 16; ++j) {
            const int d = dc + j;
            acc0 = fmaf(s_wr[0][d], w[j], acc0);
            acc1 = fmaf(s_wr[1][d], w[j], acc1);
            acc2 = fmaf(s_wr[2][d], w[j], acc2);
            acc3 = fmaf(s_wr[3][d], w[j], acc3);
        }
    }
    s_part[dh][0][e] = acc0;
    s_part[dh][1][e] = acc1;
    s_part[dh][2][e] = acc2;
    s_part[dh][3][e] = acc3;
    __syncthreads();

    {
        const int rbase = dh * 2;
        #pragma unroll
        for (int r = 0; r < 2; ++r) {
            const int rb = rbase + r;
            g_q[(long)(bb + rb) * ED + e] = s_part[0][rb][e] + s_part[1][rb][e];
        }
    }
}

// ---------- main: gather + online softmax (group rescale) + branch + LN ----------
__global__ __launch_bounds__(512, 2) void entity_encoder_kernel(
    const int*   __restrict__ conn_left,
    const int*   __restrict__ conn_right,
    const float* __restrict__ emb,
    const float* __restrict__ W_tail,
    const float* __restrict__ W_head,
    const float* __restrict__ gamma,
    const float* __restrict__ beta,
    float*       __restrict__ out)
{
    const int b    = blockIdx.x;
    const int tid  = threadIdx.x;
    const int wid  = tid >> 5;
    const int lane = tid & 31;
    const int side = wid >> 3;
    const int sw   = wid & 7;

    __shared__ float s_head[2][ED];
    __shared__ float s_q[ED];
    __shared__ int2  s_conn[2][MAXN];
    __shared__ float s_part[16][ED];
    __shared__ float s_mw[16];
    __shared__ float s_zw[16];
    __shared__ float s_agg[2][ED];
    __shared__ float s_x[2][ED];
    __shared__ float s_redA[16];
    __shared__ float s_redB[16];
    __shared__ float s_stat[2][2];

    // ---- stage conn pairs + q + heads (coalesced) ----
    {
        const int2* cl = (const int2*)(conn_left  + (long)b * MAXN * 2);
        const int2* cr = (const int2*)(conn_right + (long)b * MAXN * 2);
        for (int i = tid; i < MAXN; i += 512) {
            s_conn[0][i] = cl[i];
            s_conn[1][i] = cr[i];
        }
        if (tid < ED) {
            s_q[tid] = g_q[b * ED + tid];
        } else if (tid < 384) {
            const int sL = (tid - ED) >> 7;
            const int t  = tid & (ED - 1);
            s_head[sL][t] = g_head[((long)sL * BATCH + b) * ED + t];
        }
    }
    __syncthreads();

    // ---- SINGLE merged pass: score + online-softmax aggregate ----
    {
        const float4 q4 = ((const float4*)s_q)[lane];
        const int2*  cn = s_conn[side];

        float  wm  = -FLT_MAX;
        float  wz  = 0.f;
        float4 acc = make_float4(0.f, 0.f, 0.f, 0.f);

        #pragma unroll 1
        for (int g = 0; g < 6; ++g) {
            const int mb = sw + 32 * g;
            int2 c4[4];
            #pragma unroll
            for (int i = 0; i < 4; ++i) c4[i] = cn[mb + 8 * i];
            float4 r[4], t[4];
            #pragma unroll
            for (int i = 0; i < 4; ++i)
                r[i] = ((const float4*)(emb + (long)c4[i].x * ED))[lane];
            #pragma unroll
            for (int i = 0; i < 4; ++i)
                t[i] = ((const float4*)(emb + (long)c4[i].y * ED))[lane];

            // scores for all 4 neighbors (independent shuffle trees)
            float v[4];
            #pragma unroll
            for (int i = 0; i < 4; ++i) {
                float x = q4.x * r[i].x + q4.y * r[i].y + q4.z * r[i].z + q4.w * r[i].w;
                x += __shfl_xor_sync(FULLM, x, 16);
                x += __shfl_xor_sync(FULLM, x, 8);
                x += __shfl_xor_sync(FULLM, x, 4);
                x += __shfl_xor_sync(FULLM, x, 2);
                x += __shfl_xor_sync(FULLM, x, 1);
                if (c4[i].x == PAD_IDX) x = -FLT_MAX;
                v[i] = x;
            }

            // ONE rescale per group
            const float gm = fmaxf(fmaxf(v[0], v[1]), fmaxf(v[2], v[3]));
            const float mn = fmaxf(wm, gm);
            const float cc = __expf(wm - mn);
            float e[4];
            #pragma unroll
            for (int i = 0; i < 4; ++i) e[i] = __expf(v[i] - mn);
            wm = mn;
            wz = wz * cc + ((e[0] + e[1]) + (e[2] + e[3]));
            acc.x = fmaf(acc.x, cc, e[0] * t[0].x + e[1] * t[1].x + e[2] * t[2].x + e[3] * t[3].x);
            acc.y = fmaf(acc.y, cc, e[0] * t[0].y + e[1] * t[1].y + e[2] * t[2].y + e[3] * t[3].y);
            acc.z = fmaf(acc.z, cc, e[0] * t[0].z + e[1] * t[1].z + e[2] * t[2].z + e[3] * t[3].z);
            acc.w = fmaf(acc.w, cc, e[0] * t[0].w + e[1] * t[1].w + e[2] * t[2].w + e[3] * t[3].w);
        }
        {   // tail neighbor m = 192 + sw
            const int2 c1 = cn[192 + sw];
            float4 r = ((const float4*)(emb + (long)c1.x * ED))[lane];
            float4 t = ((const float4*)(emb + (long)c1.y * ED))[lane];
            float v = q4.x * r.x + q4.y * r.y + q4.z * r.z + q4.w * r.w;
            v += __shfl_xor_sync(FULLM, v, 16);
            v += __shfl_xor_sync(FULLM, v, 8);
            v += __shfl_xor_sync(FULLM, v, 4);
            v += __shfl_xor_sync(FULLM, v, 2);
            v += __shfl_xor_sync(FULLM, v, 1);
            if (c1.x == PAD_IDX) v = -FLT_MAX;
            const float mn = fmaxf(wm, v);
            const float cc = __expf(wm - mn);
            const float e  = __expf(v - mn);
            wm = mn;
            wz = wz * cc + e;
            acc.x = fmaf(acc.x, cc, e * t.x);
            acc.y = fmaf(acc.y, cc, e * t.y);
            acc.z = fmaf(acc.z, cc, e * t.z);
            acc.w = fmaf(acc.w, cc, e * t.w);
        }
        ((float4*)s_part[wid])[lane] = acc;
        if (lane == 0) { s_mw[wid] = wm; s_zw[wid] = wz; }
    }
    __syncthreads();

    // ---- cross-warp combine with max-correction; normalize once ----
    if (tid < 256) {
        const int sR = tid >> 7;
        const int t  = tid & (ED - 1);
        float M = -FLT_MAX;
        #pragma unroll
        for (int w = 0; w < 8; ++w) M = fmaxf(M, s_mw[sR * 8 + w]);
        float sum = 0.f, Z = 0.f;
        #pragma unroll
        for (int w = 0; w < 8; ++w) {
            const float sc = __expf(s_mw[sR * 8 + w] - M);
            sum = fmaf(sc, s_part[sR * 8 + w][t], sum);
            Z   = fmaf(sc, s_zw[sR * 8 + w], Z);
        }
        s_agg[sR][t] = sum * (1.f / Z);
    }
    __syncthreads();

    // ---- h = relu(agg.W_tail^T + head.W_head^T) for BOTH sides ----
    {
        const float4 aL = ((const float4*)s_agg[0])[lane];
        const float4 hL = ((const float4*)s_head[0])[lane];
        const float4 aR = ((const float4*)s_agg[1])[lane];
        const float4 hR = ((const float4*)s_head[1])[lane];
        #pragma unroll 1
        for (int i0 = wid; i0 < ED; i0 += 32) {
            const int i1 = i0 + 16;
            float4 wt0 = ((const float4*)(W_tail + i0 * ED))[lane];
            float4 wh0 = ((const float4*)(W_head + i0 * ED))[lane];
            float4 wt1 = ((const float4*)(W_tail + i1 * ED))[lane];
            float4 wh1 = ((const float4*)(W_head + i1 * ED))[lane];
            float vL0 = aL.x * wt0.x + aL.y * wt0.y + aL.z * wt0.z + aL.w * wt0.w
                      + hL.x * wh0.x + hL.y * wh0.y + hL.z * wh0.z + hL.w * wh0.w;
            float vR0 = aR.x * wt0.x + aR.y * wt0.y + aR.z * wt0.z + aR.w * wt0.w
                      + hR.x * wh0.x + hR.y * wh0.y + hR.z * wh0.z + hR.w * wh0.w;
            float vL1 = aL.x * wt1.x + aL.y * wt1.y + aL.z * wt1.z + aL.w * wt1.w
                      + hL.x * wh1.x + hL.y * wh1.y + hL.z * wh1.z + hL.w * wh1.w;
            float vR1 = aR.x * wt1.x + aR.y * wt1.y + aR.z * wt1.z + aR.w * wt1.w
                      + hR.x * wh1.x + hR.y * wh1.y + hR.z * wh1.z + hR.w * wh1.w;
            #pragma unroll
            for (int d = 16; d >= 1; d >>= 1) {
                vL0 += __shfl_xor_sync(FULLM, vL0, d);
                vR0 += __shfl_xor_sync(FULLM, vR0, d);
                vL1 += __shfl_xor_sync(FULLM, vL1, d);
                vR1 += __shfl_xor_sync(FULLM, vR1, d);
            }
            if (lane == 0) {
                s_x[0][i0] = fmaxf(vL0, 0.f) + s_head[0][i0];
                s_x[1][i0] = fmaxf(vR0, 0.f) + s_head[1][i0];
                s_x[0][i1] = fmaxf(vL1, 0.f) + s_head[0][i1];
                s_x[1][i1] = fmaxf(vR1, 0.f) + s_head[1][i1];
            }
        }
    }
    __syncthreads();

    // ---- two LayerNorms in parallel ----
    if (tid < 256) {
        const int sL = tid >> 7;
        const int t  = tid & (ED - 1);
        const int w4 = t >> 5;
        float xv = s_x[sL][t];
        float s1 = xv, s2 = xv * xv;
        #pragma unroll
        for (int d = 16; d >= 1; d >>= 1) {
            s1 += __shfl_xor_sync(FULLM, s1, d);
            s2 += __shfl_xor_sync(FULLM, s2, d);
        }
        if (lane == 0) { s_redA[sL * 8 + w4] = s1; s_redB[sL * 8 + w4] = s2; }
    }
    __syncthreads();
    if (tid < 256) {
        const int sL = tid >> 7;
        const int t  = tid & (ED - 1);
        if (t == 0) {
            float t1 = 0.f, t2 = 0.f;
            #pragma unroll
            for (int w = 0; w < 4; ++w) { t1 += s_redA[sL * 8 + w]; t2 += s_redB[sL * 8 + w]; }
            float mu  = t1 * (1.f / ED);
            float var = t2 * (1.f / ED) - mu * mu;
            s_stat[sL][0] = mu;
            s_stat[sL][1] = rsqrtf(var + LN_EPS);
        }
    }
    __syncthreads();
    if (tid < 256) {
        const int sL = tid >> 7;
        const int t  = tid & (ED - 1);
        float mu = s_stat[sL][0], rstd = s_stat[sL][1];
        float o = (s_x[sL][t] - mu) * rstd * gamma[t] + beta[t];
        out[((long)sL * BATCH + b) * ED + t] = o;
    }
}

extern "C" void kernel_launch(void* const* d_in, const int* in_sizes, int n_in,
                              void* d_out, int out_size) {
    (void)in_sizes; (void)n_in; (void)out_size;
    const int*   entity     = (const int*)  d_in[0];
    const int*   conn_left  = (const int*)  d_in[1];
    const int*   conn_right = (const int*)  d_in[2];
    const float* emb        = (const float*)d_in[3];
    const float* W_bil      = (const float*)d_in[4];
    const float* W_tail     = (const float*)d_in[5];
    const float* W_head     = (const float*)d_in[6];
    const float* gamma      = (const float*)d_in[7];
    const float* beta       = (const float*)d_in[8];
    float* out = (float*)d_out;

    prep_kernel<<<BATCH / PREP_ROWS, 256>>>(entity, emb, W_bil);
    entity_encoder_kernel<<<BATCH, 512>>>(conn_left, conn_right, emb,
                                          W_tail, W_head, gamma, beta, out);
}